// round 2
// baseline (speedup 1.0000x reference)
#include <cuda_runtime.h>

// Problem constants
#define NB 8
#define NC 256
#define NH 112
#define NW 112
#define HW 12544           // 112*112
#define CHW 3211264        // 256*HW
#define TOT 25690112       // 8*CHW
#define PA 196             // patch area
#define DD 16384           // C * split_head_num (256*64)
#define AG 3136            // 56*56
#define TGD 56
#define GN_BLKS 784
#define GN_CHUNK 4096      // 784*4096 = CHW exactly

// -------- device scratch (allocation-free; fully rewritten each call) --------
static __device__ float g_q[TOT];
static __device__ float g_k[TOT];
static __device__ float g_v[TOT];
static __device__ float g_qp[NB * NC * AG];
static __device__ float g_kp[NB * NC * AG];
static __device__ float g_vp[NB * NC * AG];
static __device__ float g_attp[NB * PA * PA];
static __device__ float g_attg[(size_t)NB * AG * AG];   // 315 MB
static __device__ float g_hg[NB * NC * AG];
static __device__ float g_hp[TOT];
static __device__ float g_part[NB * GN_BLKS * 2];
static __device__ float g_aff[NB * NC * 2];             // per (b,c): scale a, offset bb

// ======================= GroupNorm statistics =======================
__global__ void __launch_bounds__(256) k_gn_partial(const float* __restrict__ x) {
    int b = blockIdx.y;
    const float* xb = x + (size_t)b * CHW + (size_t)blockIdx.x * GN_CHUNK;
    float s = 0.f, s2 = 0.f;
    for (int i = threadIdx.x; i < GN_CHUNK; i += 256) {
        float v = xb[i];
        s += v; s2 += v * v;
    }
    __shared__ float sh[256], sh2[256];
    int t = threadIdx.x;
    sh[t] = s; sh2[t] = s2; __syncthreads();
    for (int o = 128; o > 0; o >>= 1) {
        if (t < o) { sh[t] += sh[t + o]; sh2[t] += sh2[t + o]; }
        __syncthreads();
    }
    if (t == 0) {
        int idx = (b * GN_BLKS + blockIdx.x) * 2;
        g_part[idx] = sh[0];
        g_part[idx + 1] = sh2[0];
    }
}

__global__ void __launch_bounds__(256) k_gn_final(const float* __restrict__ gw,
                                                  const float* __restrict__ gb) {
    int b = blockIdx.x;
    int t = threadIdx.x;
    double s = 0.0, s2 = 0.0;
    for (int i = t; i < GN_BLKS; i += 256) {
        s  += (double)g_part[(b * GN_BLKS + i) * 2];
        s2 += (double)g_part[(b * GN_BLKS + i) * 2 + 1];
    }
    __shared__ double sh[256], sh2[256];
    sh[t] = s; sh2[t] = s2; __syncthreads();
    for (int o = 128; o > 0; o >>= 1) {
        if (t < o) { sh[t] += sh[t + o]; sh2[t] += sh2[t + o]; }
        __syncthreads();
    }
    __shared__ float mu_s, rs_s;
    if (t == 0) {
        double mu = sh[0] / (double)CHW;
        double var = sh2[0] / (double)CHW - mu * mu;
        mu_s = (float)mu;
        rs_s = (float)(1.0 / sqrt(var + 1e-5));
    }
    __syncthreads();
    // per-channel affine: xn = a*x + bb
    int c = t;  // 256 threads == NC
    float a = rs_s * gw[c];
    g_aff[(b * NC + c) * 2] = a;
    g_aff[(b * NC + c) * 2 + 1] = gb[c] - mu_s * a;
}

// ======================= QKV GEMM (GN affine fused into B-tile load) =======================
// q/k/v[b,o,p] = sum_c W[o,c] * (a_c * x[b,c,p] + bb_c) + bias[o]
// Stacked M=768 (Wq|Wk|Wv), N=12544, K=256.
__global__ void __launch_bounds__(256) k_qkv(
    const float* __restrict__ x,
    const float* __restrict__ wq, const float* __restrict__ bq,
    const float* __restrict__ wk, const float* __restrict__ bk,
    const float* __restrict__ wv, const float* __restrict__ bv)
{
    int b = blockIdx.z;
    int m0 = blockIdx.y * 64;   // 0..704
    int n0 = blockIdx.x * 64;   // 0..12480
    int t = threadIdx.x;

    __shared__ float As[16][68];
    __shared__ float Bs[16][68];
    __shared__ float sa[NC], sbb[NC];
    sa[t]  = g_aff[(b * NC + t) * 2];
    sbb[t] = g_aff[(b * NC + t) * 2 + 1];

    const float* xb = x + (size_t)b * CHW;
    int tm = t >> 4, tn = t & 15;
    int a_mm = t >> 2;          // 0..63
    int a_kk = (t & 3) * 4;     // 0,4,8,12
    int b_kk = t >> 4;          // 0..15
    int b_nn = (t & 15) * 4;    // 0..60

    float acc[4][4] = {};
    __syncthreads();            // sa/sbb visible

    for (int k0 = 0; k0 < NC; k0 += 16) {
        // A: stacked weights, coalesced along k, transposed into As[kk][mm]
        int m = m0 + a_mm;
        const float* wptr = (m < NC) ? wq : (m < 2 * NC) ? wk : wv;
        int o = m & (NC - 1);
        float4 w4 = *(const float4*)(wptr + o * NC + k0 + a_kk);
        As[a_kk + 0][a_mm] = w4.x;
        As[a_kk + 1][a_mm] = w4.y;
        As[a_kk + 2][a_mm] = w4.z;
        As[a_kk + 3][a_mm] = w4.w;
        // B: x with per-channel affine
        float aa = sa[k0 + b_kk], bb = sbb[k0 + b_kk];
        float4 x4 = *(const float4*)(xb + (size_t)(k0 + b_kk) * HW + n0 + b_nn);
        float4 r;
        r.x = fmaf(x4.x, aa, bb); r.y = fmaf(x4.y, aa, bb);
        r.z = fmaf(x4.z, aa, bb); r.w = fmaf(x4.w, aa, bb);
        *(float4*)&Bs[b_kk][b_nn] = r;
        __syncthreads();
        #pragma unroll
        for (int kk = 0; kk < 16; kk++) {
            float ar[4], br[4];
            *(float4*)ar = *(const float4*)&As[kk][tm * 4];
            *(float4*)br = *(const float4*)&Bs[kk][tn * 4];
            #pragma unroll
            for (int i = 0; i < 4; i++)
                #pragma unroll
                for (int j = 0; j < 4; j++)
                    acc[i][j] += ar[i] * br[j];
        }
        __syncthreads();
    }

    #pragma unroll
    for (int i = 0; i < 4; i++) {
        int m = m0 + tm * 4 + i;
        int which = m >> 8;
        int o = m & 255;
        const float* bias = (which == 0) ? bq : (which == 1) ? bk : bv;
        float* dst = (which == 0) ? g_q : (which == 1) ? g_k : g_v;
        float bv_ = bias[o];
        float* row = dst + (size_t)b * CHW + (size_t)o * HW + n0 + tn * 4;
        float4 r;
        r.x = acc[i][0] + bv_; r.y = acc[i][1] + bv_;
        r.z = acc[i][2] + bv_; r.w = acc[i][3] + bv_;
        *(float4*)row = r;
    }
}

// ======================= 2x2 average pool (112->56) =======================
__global__ void __launch_bounds__(256) k_pool(int which) {
    int i = blockIdx.x * 256 + threadIdx.x;
    if (i >= NB * NC * AG) return;
    const float* src = (which == 0) ? g_q : (which == 1) ? g_k : g_v;
    float* dst = (which == 0) ? g_qp : (which == 1) ? g_kp : g_vp;
    int xq = i % TGD;
    int t2 = i / TGD;
    int yq = t2 % TGD;
    int bc = t2 / TGD;
    const float* s = src + (size_t)bc * HW + (size_t)(yq * 2) * NW + xq * 2;
    dst[i] = 0.25f * (s[0] + s[1] + s[NW] + s[NW + 1]);
}

// ======================= attention scores: att[p,q] = scale * sum_k Q[k,p]K[k,q] =======================
// MODE 0: patch  (M=196,  Kd=16384, scale=1/128)
// MODE 1: global (M=3136, Kd=256,   scale=1/16)
template <int MODE>
__global__ void __launch_bounds__(256) k_scores() {
    constexpr int M  = (MODE == 0) ? PA : AG;
    constexpr int Kd = (MODE == 0) ? DD : NC;
    const float scale = (MODE == 0) ? 0.0078125f : 0.0625f;
    const float* Q = (MODE == 0) ? g_q : g_qp;
    const float* K = (MODE == 0) ? g_k : g_kp;
    float* att = (MODE == 0) ? g_attp : g_attg;

    int b = blockIdx.z;
    const float* Qb = Q + (size_t)b * Kd * M;
    const float* Kb = K + (size_t)b * Kd * M;
    float* attb = att + (size_t)b * M * M;
    int m0 = blockIdx.y * 64, n0 = blockIdx.x * 64;
    int t = threadIdx.x;

    __shared__ float As[16][68], Bs[16][68];
    float acc[4][4] = {};
    int tm = t >> 4, tn = t & 15;

    for (int k0 = 0; k0 < Kd; k0 += 16) {
        #pragma unroll
        for (int r = 0; r < 4; r++) {
            int idx = t + r * 256;
            int kk = idx >> 6, c = idx & 63;
            int m = m0 + c, n = n0 + c;
            As[kk][c] = (m < M) ? Qb[(size_t)(k0 + kk) * M + m] : 0.f;
            Bs[kk][c] = (n < M) ? Kb[(size_t)(k0 + kk) * M + n] : 0.f;
        }
        __syncthreads();
        #pragma unroll
        for (int kk = 0; kk < 16; kk++) {
            float ar[4], br[4];
            *(float4*)ar = *(const float4*)&As[kk][tm * 4];
            *(float4*)br = *(const float4*)&Bs[kk][tn * 4];
            #pragma unroll
            for (int i = 0; i < 4; i++)
                #pragma unroll
                for (int j = 0; j < 4; j++)
                    acc[i][j] += ar[i] * br[j];
        }
        __syncthreads();
    }
    #pragma unroll
    for (int i = 0; i < 4; i++) {
        int m = m0 + tm * 4 + i;
        if (m >= M) continue;
        #pragma unroll
        for (int j = 0; j < 4; j++) {
            int n = n0 + tn * 4 + j;
            if (n < M) attb[(size_t)m * M + n] = acc[i][j] * scale;
        }
    }
}

// ======================= row softmax (registers-resident) =======================
template <int MODE>
__global__ void __launch_bounds__(256) k_softmax() {
    constexpr int N = (MODE == 0) ? PA : AG;
    constexpr int VL = (N + 255) / 256;
    float* att = (MODE == 0) ? g_attp : g_attg;
    float* row = att + (size_t)blockIdx.x * N;
    int t = threadIdx.x;

    float v[VL];
    float mx = -3.4e38f;
    int cnt = 0;
    for (int i = t; i < N; i += 256) { float a = row[i]; v[cnt++] = a; mx = fmaxf(mx, a); }

    __shared__ float sh[256];
    sh[t] = mx; __syncthreads();
    #pragma unroll
    for (int o = 128; o > 0; o >>= 1) { if (t < o) sh[t] = fmaxf(sh[t], sh[t + o]); __syncthreads(); }
    mx = sh[0];
    __syncthreads();

    float s = 0.f; cnt = 0;
    for (int i = t; i < N; i += 256) { float e = __expf(v[cnt] - mx); v[cnt] = e; s += e; cnt++; }
    sh[t] = s; __syncthreads();
    #pragma unroll
    for (int o = 128; o > 0; o >>= 1) { if (t < o) sh[t] += sh[t + o]; __syncthreads(); }
    float inv = 1.f / sh[0];

    cnt = 0;
    for (int i = t; i < N; i += 256) row[i] = v[cnt++] * inv;
}

// ======================= PV: h[m,n] = sum_k V[m,k] * att[n,k] =======================
// MODE 0: patch  (M=16384, N=196,  Kd=196)  -> g_hp
// MODE 1: global (M=256,   N=3136, Kd=3136) -> g_hg
template <int MODE>
__global__ void __launch_bounds__(256) k_pv() {
    constexpr int M  = (MODE == 0) ? DD : NC;
    constexpr int N  = (MODE == 0) ? PA : AG;
    constexpr int Kd = (MODE == 0) ? PA : AG;
    const float* V = (MODE == 0) ? g_v : g_vp;
    const float* att = (MODE == 0) ? g_attp : g_attg;
    float* h = (MODE == 0) ? g_hp : g_hg;

    int b = blockIdx.z;
    const float* Vb = V + (size_t)b * M * Kd;
    const float* attb = att + (size_t)b * N * Kd;
    float* hb = h + (size_t)b * M * N;
    int m0 = blockIdx.y * 64, n0 = blockIdx.x * 64;
    int t = threadIdx.x;

    __shared__ float As[16][68], Bs[16][68];
    float acc[4][4] = {};
    int tm = t >> 4, tn = t & 15;

    for (int k0 = 0; k0 < Kd; k0 += 16) {
        #pragma unroll
        for (int r = 0; r < 4; r++) {
            int idx = t + r * 256;
            int a = idx >> 4, kk = idx & 15;
            int k = k0 + kk;
            As[kk][a] = (m0 + a < M && k < Kd) ? Vb[(size_t)(m0 + a) * Kd + k] : 0.f;
            Bs[kk][a] = (n0 + a < N && k < Kd) ? attb[(size_t)(n0 + a) * Kd + k] : 0.f;
        }
        __syncthreads();
        #pragma unroll
        for (int kk = 0; kk < 16; kk++) {
            float ar[4], br[4];
            *(float4*)ar = *(const float4*)&As[kk][tm * 4];
            *(float4*)br = *(const float4*)&Bs[kk][tn * 4];
            #pragma unroll
            for (int i = 0; i < 4; i++)
                #pragma unroll
                for (int j = 0; j < 4; j++)
                    acc[i][j] += ar[i] * br[j];
        }
        __syncthreads();
    }
    #pragma unroll
    for (int i = 0; i < 4; i++) {
        int m = m0 + tm * 4 + i;
        if (m >= M) continue;
        #pragma unroll
        for (int j = 0; j < 4; j++) {
            int n = n0 + tn * 4 + j;
            if (n < N) hb[(size_t)m * N + n] = acc[i][j];
        }
    }
}

// ======================= combine: h = 0.75*h_patch + 0.25*bilinear_up(h_glob) =======================
__global__ void __launch_bounds__(256) k_combine() {
    int i = blockIdx.x * 256 + threadIdx.x;
    if (i >= TOT) return;
    int xw = i % NW;
    int t2 = i / NW;
    int yh = t2 % NH;
    int bc = t2 / NH;

    // half-pixel 2x bilinear: even idx -> (0.25 prev, 0.75 cur); odd -> (0.75 cur, 0.25 next)
    int jy = yh >> 1;
    int y0 = (yh & 1) ? jy : jy - 1;
    float wy = (yh & 1) ? 0.25f : 0.75f;
    int y1 = min(y0 + 1, TGD - 1);
    y0 = max(y0, 0);

    int jx = xw >> 1;
    int x0 = (xw & 1) ? jx : jx - 1;
    float wx = (xw & 1) ? 0.25f : 0.75f;
    int x1 = min(x0 + 1, TGD - 1);
    x0 = max(x0, 0);

    const float* g = g_hg + (size_t)bc * AG;
    float v00 = g[y0 * TGD + x0], v01 = g[y0 * TGD + x1];
    float v10 = g[y1 * TGD + x0], v11 = g[y1 * TGD + x1];
    float top = v00 * (1.f - wx) + v01 * wx;
    float bot = v10 * (1.f - wx) + v11 * wx;
    float gv = top * (1.f - wy) + bot * wy;

    g_hp[i] = 0.75f * g_hp[i] + 0.25f * gv;
}

// ======================= proj GEMM + residual =======================
__global__ void __launch_bounds__(256) k_proj(const float* __restrict__ x,
                                              const float* __restrict__ wp,
                                              float* __restrict__ out) {
    int b = blockIdx.z;
    int m0 = blockIdx.y * 64;
    int n0 = blockIdx.x * 64;
    int t = threadIdx.x;

    __shared__ float As[16][68];
    __shared__ float Bs[16][68];
    const float* hbase = g_hp + (size_t)b * CHW;
    int tm = t >> 4, tn = t & 15;
    int a_mm = t >> 2;
    int a_kk = (t & 3) * 4;
    int b_kk = t >> 4;
    int b_nn = (t & 15) * 4;
    float acc[4][4] = {};

    for (int k0 = 0; k0 < NC; k0 += 16) {
        float4 w4 = *(const float4*)(wp + (m0 + a_mm) * NC + k0 + a_kk);
        As[a_kk + 0][a_mm] = w4.x;
        As[a_kk + 1][a_mm] = w4.y;
        As[a_kk + 2][a_mm] = w4.z;
        As[a_kk + 3][a_mm] = w4.w;
        float4 h4 = *(const float4*)(hbase + (size_t)(k0 + b_kk) * HW + n0 + b_nn);
        *(float4*)&Bs[b_kk][b_nn] = h4;
        __syncthreads();
        #pragma unroll
        for (int kk = 0; kk < 16; kk++) {
            float ar[4], br[4];
            *(float4*)ar = *(const float4*)&As[kk][tm * 4];
            *(float4*)br = *(const float4*)&Bs[kk][tn * 4];
            #pragma unroll
            for (int i = 0; i < 4; i++)
                #pragma unroll
                for (int j = 0; j < 4; j++)
                    acc[i][j] += ar[i] * br[j];
        }
        __syncthreads();
    }
    #pragma unroll
    for (int i = 0; i < 4; i++) {
        int m = m0 + tm * 4 + i;
        const float* xr = x + (size_t)b * CHW + (size_t)m * HW + n0 + tn * 4;
        float* orow = out + (size_t)b * CHW + (size_t)m * HW + n0 + tn * 4;
        float4 xv = *(const float4*)xr;
        float4 r;
        r.x = acc[i][0] + xv.x; r.y = acc[i][1] + xv.y;
        r.z = acc[i][2] + xv.z; r.w = acc[i][3] + xv.w;
        *(float4*)orow = r;
    }
}

// ======================= launch =======================
extern "C" void kernel_launch(void* const* d_in, const int* in_sizes, int n_in,
                              void* d_out, int out_size) {
    const float* x   = (const float*)d_in[0];
    const float* gnw = (const float*)d_in[1];
    const float* gnb = (const float*)d_in[2];
    const float* wq  = (const float*)d_in[3];
    const float* bq  = (const float*)d_in[4];
    const float* wk  = (const float*)d_in[5];
    const float* bk  = (const float*)d_in[6];
    const float* wv  = (const float*)d_in[7];
    const float* bv  = (const float*)d_in[8];
    const float* wp  = (const float*)d_in[9];
    float* out = (float*)d_out;

    // GroupNorm stats + affine fold
    k_gn_partial<<<dim3(GN_BLKS, NB), 256>>>(x);
    k_gn_final<<<NB, 256>>>(gnw, gnb);

    // QKV (GN fused)
    k_qkv<<<dim3(HW / 64, 12, NB), 256>>>(x, wq, bq, wk, bk, wv, bv);

    // pooled q,k,v
    int pool_blocks = (NB * NC * AG + 255) / 256;
    k_pool<<<pool_blocks, 256>>>(0);
    k_pool<<<pool_blocks, 256>>>(1);
    k_pool<<<pool_blocks, 256>>>(2);

    // patch attention
    k_scores<0><<<dim3(4, 4, NB), 256>>>();
    k_softmax<0><<<NB * PA, 256>>>();
    k_pv<0><<<dim3(4, DD / 64, NB), 256>>>();

    // global attention
    k_scores<1><<<dim3(AG / 64, AG / 64, NB), 256>>>();
    k_softmax<1><<<NB * AG, 256>>>();
    k_pv<1><<<dim3(AG / 64, 4, NB), 256>>>();

    // combine + upsample
    k_combine<<<(TOT + 255) / 256, 256>>>();

    // proj + residual
    k_proj<<<dim3(HW / 64, 4, NB), 256>>>(x, wp, out);
}

// round 3
// speedup vs baseline: 2.0412x; 2.0412x over previous
#include <cuda_runtime.h>
#include <cstdint>

// Problem constants
#define NB 8
#define NC 256
#define NH 112
#define NW 112
#define HW 12544           // 112*112
#define CHW 3211264        // 256*HW
#define TOT 25690112       // 8*CHW
#define PA 196             // patch area
#define DD 16384           // C * split_head_num (256*64)
#define AG 3136            // 56*56
#define TGD 56
#define GN_BLKS 784
#define GN_CHUNK 4096      // 784*4096 = CHW exactly

// -------- device scratch (allocation-free; fully rewritten each call) --------
static __device__ float g_qkv[(size_t)3 * TOT];          // q|k|v stacked
static __device__ float g_xn[TOT];                       // normalized x
static __device__ float g_qp[NB * NC * AG];
static __device__ float g_kp[NB * NC * AG];
static __device__ float g_vp[NB * NC * AG];
static __device__ float g_attp[NB * PA * PA];
static __device__ float g_attg[(size_t)NB * AG * AG];    // 315 MB
static __device__ float g_hg[NB * NC * AG];
static __device__ float g_hp[TOT];
static __device__ float g_part[NB * GN_BLKS * 2];
static __device__ float g_aff[NB * NC * 2];
static __device__ float g_wqkvt[256 * 768];              // W^T stacked [K=256][M=768]
static __device__ float g_bstack[768];

// ======================= helpers =======================
__device__ __forceinline__ float to_tf32(float x) {
    uint32_t u;
    asm("cvt.rna.tf32.f32 %0, %1;" : "=r"(u) : "f"(x));
    return __uint_as_float(u);
}

__device__ __forceinline__ void mma_tf32(float* d, const uint32_t* a, const uint32_t* b) {
    asm volatile(
        "mma.sync.aligned.m16n8k8.row.col.f32.tf32.tf32.f32 "
        "{%0,%1,%2,%3}, {%4,%5,%6,%7}, {%8,%9}, {%0,%1,%2,%3};\n"
        : "+f"(d[0]), "+f"(d[1]), "+f"(d[2]), "+f"(d[3])
        : "r"(a[0]), "r"(a[1]), "r"(a[2]), "r"(a[3]),
          "r"(b[0]), "r"(b[1]));
}

// ======================= GroupNorm statistics =======================
__global__ void __launch_bounds__(256) k_gn_partial(const float* __restrict__ x) {
    int b = blockIdx.y;
    const float* xb = x + (size_t)b * CHW + (size_t)blockIdx.x * GN_CHUNK;
    float s = 0.f, s2 = 0.f;
    for (int i = threadIdx.x; i < GN_CHUNK; i += 256) {
        float v = xb[i];
        s += v; s2 += v * v;
    }
    __shared__ float sh[256], sh2[256];
    int t = threadIdx.x;
    sh[t] = s; sh2[t] = s2; __syncthreads();
    for (int o = 128; o > 0; o >>= 1) {
        if (t < o) { sh[t] += sh[t + o]; sh2[t] += sh2[t + o]; }
        __syncthreads();
    }
    if (t == 0) {
        int idx = (b * GN_BLKS + blockIdx.x) * 2;
        g_part[idx] = sh[0];
        g_part[idx + 1] = sh2[0];
    }
}

__global__ void __launch_bounds__(256) k_gn_final(const float* __restrict__ gw,
                                                  const float* __restrict__ gb) {
    int b = blockIdx.x;
    int t = threadIdx.x;
    double s = 0.0, s2 = 0.0;
    for (int i = t; i < GN_BLKS; i += 256) {
        s  += (double)g_part[(b * GN_BLKS + i) * 2];
        s2 += (double)g_part[(b * GN_BLKS + i) * 2 + 1];
    }
    __shared__ double sh[256], sh2[256];
    sh[t] = s; sh2[t] = s2; __syncthreads();
    for (int o = 128; o > 0; o >>= 1) {
        if (t < o) { sh[t] += sh[t + o]; sh2[t] += sh2[t + o]; }
        __syncthreads();
    }
    __shared__ float mu_s, rs_s;
    if (t == 0) {
        double mu = sh[0] / (double)CHW;
        double var = sh2[0] / (double)CHW - mu * mu;
        mu_s = (float)mu;
        rs_s = (float)(1.0 / sqrt(var + 1e-5));
    }
    __syncthreads();
    int c = t;
    float a = rs_s * gw[c];
    g_aff[(b * NC + c) * 2] = a;
    g_aff[(b * NC + c) * 2 + 1] = gb[c] - mu_s * a;
}

// apply GN affine -> g_xn
__global__ void __launch_bounds__(256) k_gn_apply(const float* __restrict__ x) {
    size_t i = (size_t)blockIdx.x * 256 + threadIdx.x;   // float4 index
    if (i >= TOT / 4) return;
    size_t e = i * 4;
    int bc = (int)(e / HW);
    float a  = g_aff[bc * 2];
    float bb = g_aff[bc * 2 + 1];
    float4 v = ((const float4*)x)[i];
    v.x = fmaf(v.x, a, bb); v.y = fmaf(v.y, a, bb);
    v.z = fmaf(v.z, a, bb); v.w = fmaf(v.w, a, bb);
    ((float4*)g_xn)[i] = v;
}

// stack + transpose qkv weights, stack biases
__global__ void __launch_bounds__(256) k_prep(
    const float* __restrict__ wq, const float* __restrict__ wk, const float* __restrict__ wv,
    const float* __restrict__ bq, const float* __restrict__ bk, const float* __restrict__ bv)
{
    int i = blockIdx.x * 256 + threadIdx.x;
    if (i < 768 * 256) {
        int m = i % 768;
        int k = i / 768;
        const float* w = (m < 256) ? wq : (m < 512) ? wk : wv;
        g_wqkvt[i] = w[(m & 255) * 256 + k];
    }
    if (i < 768) {
        g_bstack[i] = (i < 256) ? bq[i] : (i < 512) ? bk[i - 256] : bv[i - 512];
    }
}

// ======================= tensor-core tf32 GEMM =======================
// C[m,n] = sum_k Aop[k][m] * Bop[k][n]
// TRA=0: A stored [K, ldA>=M] m-contig.  TRA=1: A stored [M, ldA>=K] k-contig.
// TRB mirrors for B/N.
// EPI 0: C[m*N+n] = acc*scale
// EPI 1: C[m*N+n] = acc
// EPI 2: qkv route: which=m>>8, o=m&255 -> C[which*TOT + b*CHW + o*HW + n] + aux[m]
// EPI 3: C[m*N+n] = acc + aux[b*strAux + m*N+n]
template<int BM, int BN, int TRA, int TRB, int EPI>
__global__ void __launch_bounds__(256) gemm_tc(
    const float* __restrict__ A, const float* __restrict__ Bp, float* __restrict__ C,
    int M, int N, int Kd, int ldA, int ldB,
    size_t strA, size_t strB, size_t strC,
    float scale, const float* __restrict__ aux, size_t strAux)
{
    constexpr int KT = 16;
    constexpr int WM = BM / 2, WN = BN / 4;
    constexpr int MF = WM / 16, NF = WN / 8;
    constexpr int NA4 = (KT * BM) / 1024;
    constexpr int NB4 = (KT * BN) / 1024;

    __shared__ float As[2][KT][BM + 8];
    __shared__ float Bs[2][KT][BN + 8];

    int b = blockIdx.z;
    const float* Ab = A + (size_t)b * strA;
    const float* Bb = Bp + (size_t)b * strB;
    int m0 = blockIdx.y * BM, n0 = blockIdx.x * BN;
    int tid = threadIdx.x;
    int warp = tid >> 5, lane = tid & 31;
    int wm0 = (warp & 1) * WM, wn0 = (warp >> 1) * WN;
    int gid = lane >> 2, tig = lane & 3;

    float acc[MF][NF][4];
    #pragma unroll
    for (int i = 0; i < MF; i++)
        #pragma unroll
        for (int j = 0; j < NF; j++)
            #pragma unroll
            for (int r = 0; r < 4; r++) acc[i][j][r] = 0.f;

    const float4 f40 = make_float4(0.f, 0.f, 0.f, 0.f);

    auto loadA = [&](int k0, float4* r) {
        #pragma unroll
        for (int p = 0; p < NA4; p++) {
            int idx = tid + p * 256;
            if constexpr (TRA == 0) {
                int kk = idx / (BM / 4), mq = idx % (BM / 4);
                int gk = k0 + kk, gm = m0 + mq * 4;
                r[p] = (gk < Kd && gm < M) ? *(const float4*)(Ab + (size_t)gk * ldA + gm) : f40;
            } else {
                int m = idx >> 2, kq = idx & 3;
                int gm = m0 + m, gk = k0 + kq * 4;
                r[p] = (gm < M && gk < Kd) ? *(const float4*)(Ab + (size_t)gm * ldA + gk) : f40;
            }
        }
    };
    auto loadB = [&](int k0, float4* r) {
        #pragma unroll
        for (int p = 0; p < NB4; p++) {
            int idx = tid + p * 256;
            if constexpr (TRB == 0) {
                int kk = idx / (BN / 4), nq = idx % (BN / 4);
                int gk = k0 + kk, gn = n0 + nq * 4;
                r[p] = (gk < Kd && gn < N) ? *(const float4*)(Bb + (size_t)gk * ldB + gn) : f40;
            } else {
                int n = idx >> 2, kq = idx & 3;
                int gn = n0 + n, gk = k0 + kq * 4;
                r[p] = (gn < N && gk < Kd) ? *(const float4*)(Bb + (size_t)gn * ldB + gk) : f40;
            }
        }
    };
    auto storeA = [&](int buf, const float4* r) {
        #pragma unroll
        for (int p = 0; p < NA4; p++) {
            int idx = tid + p * 256;
            if constexpr (TRA == 0) {
                int kk = idx / (BM / 4), mq = idx % (BM / 4);
                As[buf][kk][mq * 4 + 0] = to_tf32(r[p].x);
                As[buf][kk][mq * 4 + 1] = to_tf32(r[p].y);
                As[buf][kk][mq * 4 + 2] = to_tf32(r[p].z);
                As[buf][kk][mq * 4 + 3] = to_tf32(r[p].w);
            } else {
                int m = idx >> 2, kq = idx & 3;
                As[buf][kq * 4 + 0][m] = to_tf32(r[p].x);
                As[buf][kq * 4 + 1][m] = to_tf32(r[p].y);
                As[buf][kq * 4 + 2][m] = to_tf32(r[p].z);
                As[buf][kq * 4 + 3][m] = to_tf32(r[p].w);
            }
        }
    };
    auto storeB = [&](int buf, const float4* r) {
        #pragma unroll
        for (int p = 0; p < NB4; p++) {
            int idx = tid + p * 256;
            if constexpr (TRB == 0) {
                int kk = idx / (BN / 4), nq = idx % (BN / 4);
                Bs[buf][kk][nq * 4 + 0] = to_tf32(r[p].x);
                Bs[buf][kk][nq * 4 + 1] = to_tf32(r[p].y);
                Bs[buf][kk][nq * 4 + 2] = to_tf32(r[p].z);
                Bs[buf][kk][nq * 4 + 3] = to_tf32(r[p].w);
            } else {
                int n = idx >> 2, kq = idx & 3;
                Bs[buf][kq * 4 + 0][n] = to_tf32(r[p].x);
                Bs[buf][kq * 4 + 1][n] = to_tf32(r[p].y);
                Bs[buf][kq * 4 + 2][n] = to_tf32(r[p].z);
                Bs[buf][kq * 4 + 3][n] = to_tf32(r[p].w);
            }
        }
    };

    int T = (Kd + KT - 1) / KT;
    float4 ra[NA4], rb[NB4];
    loadA(0, ra); loadB(0, rb);
    storeA(0, ra); storeB(0, rb);
    __syncthreads();

    for (int t = 0; t < T; t++) {
        int cur = t & 1;
        bool nxt = (t + 1 < T);
        if (nxt) { loadA((t + 1) * KT, ra); loadB((t + 1) * KT, rb); }

        #pragma unroll
        for (int s = 0; s < 2; s++) {
            uint32_t af[MF][4], bf[NF][2];
            #pragma unroll
            for (int i = 0; i < MF; i++) {
                int rbase = wm0 + i * 16;
                af[i][0] = __float_as_uint(As[cur][s * 8 + tig    ][rbase + gid    ]);
                af[i][1] = __float_as_uint(As[cur][s * 8 + tig    ][rbase + gid + 8]);
                af[i][2] = __float_as_uint(As[cur][s * 8 + tig + 4][rbase + gid    ]);
                af[i][3] = __float_as_uint(As[cur][s * 8 + tig + 4][rbase + gid + 8]);
            }
            #pragma unroll
            for (int j = 0; j < NF; j++) {
                int cb = wn0 + j * 8;
                bf[j][0] = __float_as_uint(Bs[cur][s * 8 + tig    ][cb + gid]);
                bf[j][1] = __float_as_uint(Bs[cur][s * 8 + tig + 4][cb + gid]);
            }
            #pragma unroll
            for (int i = 0; i < MF; i++)
                #pragma unroll
                for (int j = 0; j < NF; j++)
                    mma_tf32(acc[i][j], af[i], bf[j]);
        }

        if (nxt) { storeA(cur ^ 1, ra); storeB(cur ^ 1, rb); }
        __syncthreads();
    }

    // epilogue
    float* Cb = C + (size_t)b * strC;
    const float* auxb = aux ? (aux + (size_t)b * strAux) : nullptr;

    auto epi_store = [&](int r, int c, float v) {
        if constexpr (EPI == 0) {
            Cb[(size_t)r * N + c] = v * scale;
        } else if constexpr (EPI == 1) {
            Cb[(size_t)r * N + c] = v;
        } else if constexpr (EPI == 2) {
            int which = r >> 8, o = r & 255;
            C[(size_t)which * TOT + (size_t)b * CHW + (size_t)o * HW + c] = v + aux[r];
        } else {
            Cb[(size_t)r * N + c] = v + auxb[(size_t)r * N + c];
        }
    };

    #pragma unroll
    for (int i = 0; i < MF; i++) {
        int r0 = m0 + wm0 + i * 16 + gid;
        int r1 = r0 + 8;
        #pragma unroll
        for (int j = 0; j < NF; j++) {
            int cb = n0 + wn0 + j * 8 + tig * 2;
            if (cb < N) {
                if (r0 < M) { epi_store(r0, cb, acc[i][j][0]); epi_store(r0, cb + 1, acc[i][j][1]); }
                if (r1 < M) { epi_store(r1, cb, acc[i][j][2]); epi_store(r1, cb + 1, acc[i][j][3]); }
            }
        }
    }
}

// ======================= 2x2 average pool (112->56), 3 tensors =======================
__global__ void __launch_bounds__(256) k_pool() {
    int which = blockIdx.y;
    int i = blockIdx.x * 256 + threadIdx.x;
    if (i >= NB * NC * AG) return;
    const float* src = g_qkv + (size_t)which * TOT;
    float* dst = (which == 0) ? g_qp : (which == 1) ? g_kp : g_vp;
    int xq = i % TGD;
    int t2 = i / TGD;
    int yq = t2 % TGD;
    int bc = t2 / TGD;
    const float* s = src + (size_t)bc * HW + (size_t)(yq * 2) * NW + xq * 2;
    dst[i] = 0.25f * (s[0] + s[1] + s[NW] + s[NW + 1]);
}

// ======================= row softmax =======================
template <int MODE>
__global__ void __launch_bounds__(256) k_softmax() {
    constexpr int N = (MODE == 0) ? PA : AG;
    constexpr int VL = (N + 255) / 256;
    float* att = (MODE == 0) ? g_attp : g_attg;
    float* row = att + (size_t)blockIdx.x * N;
    int t = threadIdx.x;

    float v[VL];
    float mx = -3.4e38f;
    int cnt = 0;
    for (int i = t; i < N; i += 256) { float a = row[i]; v[cnt++] = a; mx = fmaxf(mx, a); }

    __shared__ float sh[256];
    sh[t] = mx; __syncthreads();
    #pragma unroll
    for (int o = 128; o > 0; o >>= 1) { if (t < o) sh[t] = fmaxf(sh[t], sh[t + o]); __syncthreads(); }
    mx = sh[0];
    __syncthreads();

    float s = 0.f; cnt = 0;
    for (int i = t; i < N; i += 256) { float e = __expf(v[cnt] - mx); v[cnt] = e; s += e; cnt++; }
    sh[t] = s; __syncthreads();
    #pragma unroll
    for (int o = 128; o > 0; o >>= 1) { if (t < o) sh[t] += sh[t + o]; __syncthreads(); }
    float inv = 1.f / sh[0];

    cnt = 0;
    for (int i = t; i < N; i += 256) row[i] = v[cnt++] * inv;
}

// ======================= combine: h = 0.75*h_patch + 0.25*bilinear_up(h_glob) =======================
__global__ void __launch_bounds__(256) k_combine() {
    int i = blockIdx.x * 256 + threadIdx.x;
    if (i >= TOT) return;
    int xw = i % NW;
    int t2 = i / NW;
    int yh = t2 % NH;
    int bc = t2 / NH;

    int jy = yh >> 1;
    int y0 = (yh & 1) ? jy : jy - 1;
    float wy = (yh & 1) ? 0.25f : 0.75f;
    int y1 = min(y0 + 1, TGD - 1);
    y0 = max(y0, 0);

    int jx = xw >> 1;
    int x0 = (xw & 1) ? jx : jx - 1;
    float wx = (xw & 1) ? 0.25f : 0.75f;
    int x1 = min(x0 + 1, TGD - 1);
    x0 = max(x0, 0);

    const float* g = g_hg + (size_t)bc * AG;
    float v00 = g[y0 * TGD + x0], v01 = g[y0 * TGD + x1];
    float v10 = g[y1 * TGD + x0], v11 = g[y1 * TGD + x1];
    float top = v00 * (1.f - wx) + v01 * wx;
    float bot = v10 * (1.f - wx) + v11 * wx;
    float gv = top * (1.f - wy) + bot * wy;

    g_hp[i] = 0.75f * g_hp[i] + 0.25f * gv;
}

// ======================= launch =======================
extern "C" void kernel_launch(void* const* d_in, const int* in_sizes, int n_in,
                              void* d_out, int out_size) {
    const float* x   = (const float*)d_in[0];
    const float* gnw = (const float*)d_in[1];
    const float* gnb = (const float*)d_in[2];
    const float* wq  = (const float*)d_in[3];
    const float* bq  = (const float*)d_in[4];
    const float* wk  = (const float*)d_in[5];
    const float* bk  = (const float*)d_in[6];
    const float* wv  = (const float*)d_in[7];
    const float* bv  = (const float*)d_in[8];
    const float* wp  = (const float*)d_in[9];
    float* out = (float*)d_out;

    void* p;
    cudaGetSymbolAddress(&p, g_qkv);   float* qkv    = (float*)p;
    cudaGetSymbolAddress(&p, g_xn);    float* xn     = (float*)p;
    cudaGetSymbolAddress(&p, g_qp);    float* qp     = (float*)p;
    cudaGetSymbolAddress(&p, g_kp);    float* kp     = (float*)p;
    cudaGetSymbolAddress(&p, g_vp);    float* vp     = (float*)p;
    cudaGetSymbolAddress(&p, g_attp);  float* attp   = (float*)p;
    cudaGetSymbolAddress(&p, g_attg);  float* attg   = (float*)p;
    cudaGetSymbolAddress(&p, g_hg);    float* hg     = (float*)p;
    cudaGetSymbolAddress(&p, g_hp);    float* hp     = (float*)p;
    cudaGetSymbolAddress(&p, g_wqkvt); float* wqkvt  = (float*)p;
    cudaGetSymbolAddress(&p, g_bstack);float* bstack = (float*)p;

    float* q = qkv;
    float* k = qkv + (size_t)TOT;
    float* v = qkv + (size_t)2 * TOT;

    // GroupNorm
    k_gn_partial<<<dim3(GN_BLKS, NB), 256>>>(x);
    k_gn_final<<<NB, 256>>>(gnw, gnb);
    k_gn_apply<<<(TOT / 4 + 255) / 256, 256>>>(x);
    k_prep<<<768, 256>>>(wq, wk, wv, bq, bk, bv);

    // QKV: [768,12544] = Wt[256][768]^T-op x xn[256][12544]
    gemm_tc<128, 128, 0, 0, 2><<<dim3(98, 6, NB), 256>>>(
        wqkvt, xn, qkv, 768, HW, 256, 768, HW,
        0, CHW, 0, 1.f, bstack, 0);

    // pooled q,k,v
    int pool_blocks = (NB * NC * AG + 255) / 256;
    k_pool<<<dim3(pool_blocks, 3), 256>>>();

    // patch attention
    gemm_tc<64, 64, 0, 0, 0><<<dim3(4, 4, NB), 256>>>(
        q, k, attp, PA, PA, DD, PA, PA,
        CHW, CHW, (size_t)PA * PA, 0.0078125f, nullptr, 0);
    k_softmax<0><<<NB * PA, 256>>>();
    gemm_tc<128, 128, 1, 1, 1><<<dim3(2, 128, NB), 256>>>(
        v, attp, hp, DD, PA, PA, PA, PA,
        CHW, (size_t)PA * PA, CHW, 1.f, nullptr, 0);

    // global attention
    gemm_tc<128, 128, 0, 0, 0><<<dim3(25, 25, NB), 256>>>(
        qp, kp, attg, AG, AG, NC, AG, AG,
        (size_t)NC * AG, (size_t)NC * AG, (size_t)AG * AG, 0.0625f, nullptr, 0);
    k_softmax<1><<<NB * AG, 256>>>();
    gemm_tc<128, 128, 1, 1, 1><<<dim3(25, 2, NB), 256>>>(
        vp, attg, hg, NC, AG, AG, AG, AG,
        (size_t)NC * AG, (size_t)AG * AG, (size_t)NC * AG, 1.f, nullptr, 0);

    // combine + upsample
    k_combine<<<(TOT + 255) / 256, 256>>>();

    // proj + residual
    gemm_tc<128, 128, 1, 0, 3><<<dim3(98, 2, NB), 256>>>(
        wp, hp, out, NC, HW, NC, NC, HW,
        0, CHW, CHW, 1.f, x, CHW);
}

// round 9
// speedup vs baseline: 4.2681x; 2.0910x over previous
#include <cuda_runtime.h>
#include <cuda_bf16.h>
#include <cstdint>

// Problem constants
#define NB 8
#define NC 256
#define NHH 112
#define NWW 112
#define HW 12544
#define CHW 3211264
#define TOT 25690112
#define PA 196
#define PAP 224             // PA padded to multiple of 32
#define SHN 64
#define DD 16384            // NC * SHN
#define AG 3136             // 56*56
#define TGD 56
#define GN_BLKS 784
#define GN_CHUNK 4096
#define PSPLIT 8
#define PKS (DD / PSPLIT)   // 2048

// -------- device scratch (allocation-free; fully rewritten each call) --------
static __device__ __align__(16) __nv_bfloat16 g_xnT[TOT];                 // [b][hw][c]
static __device__ __align__(16) __nv_bfloat16 g_wstack[768 * 256];
static __device__ __align__(16) __nv_bfloat16 g_wp[256 * 256];
static __device__ float g_bstack[768];
static __device__ float g_qkv[(size_t)3 * TOT];                           // fp32 q|k|v [b][c][hw]
static __device__ __align__(16) __nv_bfloat16 g_qpT[NB * AG * NC];        // [b][p56][c]
static __device__ __align__(16) __nv_bfloat16 g_kpT[NB * AG * NC];
static __device__ __align__(16) __nv_bfloat16 g_vp[NB * NC * AG];         // [b][c][p56]
static __device__ __align__(16) __nv_bfloat16 g_qpk[(size_t)NB * PA * DD];// [b][p][d]
static __device__ __align__(16) __nv_bfloat16 g_kpk[(size_t)NB * PA * DD];
static __device__ __align__(16) __nv_bfloat16 g_vpk[(size_t)NB * DD * PAP];// [b][d][p-pad]
static __device__ float g_attps[(size_t)NB * PSPLIT * PA * PA];
static __device__ float g_attp[NB * PA * PA];
static __device__ __align__(16) __nv_bfloat16 g_attp_bf[NB * PA * PAP];
static __device__ float g_attg[(size_t)NB * AG * AG];                     // 315 MB
static __device__ __align__(16) __nv_bfloat16 g_attg_bf[(size_t)NB * AG * AG];
static __device__ float g_hg[NB * NC * AG];
static __device__ float g_hp[TOT];
static __device__ __align__(16) __nv_bfloat16 g_hT[TOT];                  // [b][hw][c]
static __device__ float g_part[NB * GN_BLKS * 2];
static __device__ float g_aff[NB * NC * 2];

// ======================= asm helpers (sm_80+ legacy path) =======================
__device__ __forceinline__ uint32_t s2u(const void* p) {
    uint32_t a;
    asm("{ .reg .u64 t; cvta.to.shared.u64 t, %1; cvt.u32.u64 %0, t; }" : "=r"(a) : "l"(p));
    return a;
}
__device__ __forceinline__ void cpa16(uint32_t dst, const void* src) {
    asm volatile("cp.async.cg.shared.global [%0], [%1], 16;"
                 :: "r"(dst), "l"(src) : "memory");
}
__device__ __forceinline__ void cpa_commit() {
    asm volatile("cp.async.commit_group;" ::: "memory");
}
__device__ __forceinline__ void ldmx4(uint32_t& r0, uint32_t& r1, uint32_t& r2, uint32_t& r3,
                                      uint32_t addr) {
    asm volatile("ldmatrix.sync.aligned.m8n8.x4.shared.b16 {%0,%1,%2,%3}, [%4];"
                 : "=r"(r0), "=r"(r1), "=r"(r2), "=r"(r3) : "r"(addr));
}
__device__ __forceinline__ void mma_bf16(float* c, const uint32_t* a, const uint32_t* b) {
    asm volatile(
        "mma.sync.aligned.m16n8k16.row.col.f32.bf16.bf16.f32 "
        "{%0,%1,%2,%3},{%4,%5,%6,%7},{%8,%9},{%0,%1,%2,%3};"
        : "+f"(c[0]), "+f"(c[1]), "+f"(c[2]), "+f"(c[3])
        : "r"(a[0]), "r"(a[1]), "r"(a[2]), "r"(a[3]), "r"(b[0]), "r"(b[1]));
}

// ======================= GroupNorm statistics =======================
__global__ void __launch_bounds__(256) k_gn_partial(const float* __restrict__ x) {
    int b = blockIdx.y;
    const float* xb = x + (size_t)b * CHW + (size_t)blockIdx.x * GN_CHUNK;
    float s = 0.f, s2 = 0.f;
    for (int i = threadIdx.x; i < GN_CHUNK; i += 256) {
        float v = xb[i];
        s += v; s2 += v * v;
    }
    __shared__ float sh[256], sh2[256];
    int t = threadIdx.x;
    sh[t] = s; sh2[t] = s2; __syncthreads();
    for (int o = 128; o > 0; o >>= 1) {
        if (t < o) { sh[t] += sh[t + o]; sh2[t] += sh2[t + o]; }
        __syncthreads();
    }
    if (t == 0) {
        int idx = (b * GN_BLKS + blockIdx.x) * 2;
        g_part[idx] = sh[0];
        g_part[idx + 1] = sh2[0];
    }
}

__global__ void __launch_bounds__(256) k_gn_final(const float* __restrict__ gw,
                                                  const float* __restrict__ gb) {
    int b = blockIdx.x;
    int t = threadIdx.x;
    double s = 0.0, s2 = 0.0;
    for (int i = t; i < GN_BLKS; i += 256) {
        s  += (double)g_part[(b * GN_BLKS + i) * 2];
        s2 += (double)g_part[(b * GN_BLKS + i) * 2 + 1];
    }
    __shared__ double sh[256], sh2[256];
    sh[t] = s; sh2[t] = s2; __syncthreads();
    for (int o = 128; o > 0; o >>= 1) {
        if (t < o) { sh[t] += sh[t + o]; sh2[t] += sh2[t + o]; }
        __syncthreads();
    }
    __shared__ float mu_s, rs_s;
    if (t == 0) {
        double mu = sh[0] / (double)CHW;
        double var = sh2[0] / (double)CHW - mu * mu;
        mu_s = (float)mu;
        rs_s = (float)(1.0 / sqrt(var + 1e-5));
    }
    __syncthreads();
    int c = t;
    float a = rs_s * gw[c];
    g_aff[(b * NC + c) * 2] = a;
    g_aff[(b * NC + c) * 2 + 1] = gb[c] - mu_s * a;
}

// ======================= GN apply + transpose -> xnT bf16 [b][hw][c] =======================
__global__ void __launch_bounds__(256) k_gn_applyT(const float* __restrict__ x) {
    __shared__ float sm[32][33];
    int b = blockIdx.z;
    int hw0 = blockIdx.x * 32, c0 = blockIdx.y * 32;
    int tx = threadIdx.x & 31, ty = threadIdx.x >> 5;
    #pragma unroll
    for (int w = 0; w < 4; w++) {
        int c = c0 + ty + w * 8;
        float a  = g_aff[(b * NC + c) * 2];
        float bb = g_aff[(b * NC + c) * 2 + 1];
        sm[ty + w * 8][tx] = fmaf(x[(size_t)b * CHW + (size_t)c * HW + hw0 + tx], a, bb);
    }
    __syncthreads();
    #pragma unroll
    for (int w = 0; w < 4; w++) {
        int hw = hw0 + ty + w * 8;
        g_xnT[(size_t)b * CHW + (size_t)hw * NC + c0 + tx] = __float2bfloat16(sm[tx][ty + w * 8]);
    }
}

// ======================= weight/bias prep =======================
__global__ void __launch_bounds__(256) k_prep(
    const float* __restrict__ wq, const float* __restrict__ wk, const float* __restrict__ wv,
    const float* __restrict__ bq, const float* __restrict__ bk, const float* __restrict__ bv,
    const float* __restrict__ wp)
{
    int i = blockIdx.x * 256 + threadIdx.x;
    if (i < 768 * 256) {
        int m = i >> 8, k = i & 255;
        const float* w = (m < 256) ? wq : (m < 512) ? wk : wv;
        g_wstack[i] = __float2bfloat16(w[(m & 255) * 256 + k]);
    }
    if (i < 256 * 256) g_wp[i] = __float2bfloat16(wp[i]);
    if (i < 768) {
        g_bstack[i] = (i < 256) ? bq[i] : (i < 512) ? bk[i - 256] : bv[i - 512];
    }
}

// ======================= bf16 mma.sync GEMM, cp.async 4-stage =======================
// D[M,N] = sum_k A[m,k]*B[n,k], A/B bf16 K-major. K multiple of 32.
// OOB row handling: row index is CLAMPED to M-1/N-1 (always-valid reads);
// clamped rows produce garbage accumulators whose stores are guarded below.
// EPI 0: C[z*strC + r*N + n] = v*scale
// EPI 1: QKV route: which=r>>8, o=r&255 -> C[which*TOT + b*CHW + o*HW + n] + aux[r]
// EPI 2: C[b*strC + r*N + n] = v + aux[b*strAux + r*N + n]
#define RSB 80          // padded SMEM row bytes (32 bf16 data + pad) -> conflict-free
#define STAGE_B 10240   // 128 rows * RSB
#define NSTAGE 4

template<int EPI>
__global__ void __launch_bounds__(256) gemm_bf(
    const __nv_bfloat16* __restrict__ A, const __nv_bfloat16* __restrict__ B,
    float* __restrict__ C,
    int M, int N, int K, int lda, int ldb,
    size_t strA, size_t strB, size_t strC,
    int nsplit, float scale, const float* __restrict__ aux, size_t strAux)
{
    extern __shared__ __align__(16) char dsm[];
    uint32_t smA = s2u(dsm);
    uint32_t smB = smA + NSTAGE * STAGE_B;

    int tid = threadIdx.x, warp = tid >> 5, lane = tid & 31;
    int z = blockIdx.z, b = z / nsplit, sp = z - b * nsplit;
    const __nv_bfloat16* Ab = A + b * strA + (size_t)sp * K;
    const __nv_bfloat16* Bb = B + b * strB + (size_t)sp * K;
    int m0 = blockIdx.y * 128, n0 = blockIdx.x * 128;

    int wm0 = (warp & 1) * 64, wn0 = (warp >> 1) * 32;
    int gid = lane >> 2, tid4 = lane & 3;

    // loader indices: 2 chunks per operand per thread; clamped = always-valid
    int lr = tid >> 2, lc = tid & 3;
    int ra1 = min(m0 + lr, M - 1);
    int ra2 = min(m0 + lr + 64, M - 1);
    int rb1 = min(n0 + lr, N - 1);
    int rb2 = min(n0 + lr + 64, N - 1);

    auto load_stage = [&](int t, int s) {
        int k0 = t << 5;
        uint32_t da = smA + s * STAGE_B + lr * RSB + lc * 16;
        uint32_t db = smB + s * STAGE_B + lr * RSB + lc * 16;
        cpa16(da,            Ab + (size_t)ra1 * lda + k0 + lc * 8);
        cpa16(db,            Bb + (size_t)rb1 * ldb + k0 + lc * 8);
        cpa16(da + 64 * RSB, Ab + (size_t)ra2 * lda + k0 + lc * 8);
        cpa16(db + 64 * RSB, Bb + (size_t)rb2 * ldb + k0 + lc * 8);
        cpa_commit();
    };

    float acc[4][4][4];
    #pragma unroll
    for (int i = 0; i < 4; i++)
        #pragma unroll
        for (int j = 0; j < 4; j++)
            #pragma unroll
            for (int r = 0; r < 4; r++) acc[i][j][r] = 0.f;

    int T = K >> 5;
    #pragma unroll
    for (int s = 0; s < NSTAGE - 1; s++) load_stage(s, s);

    // per-thread fragment addresses
    uint32_t aAddr = (uint32_t)((wm0 + (lane & 15)) * RSB + (lane >> 4) * 16);
    uint32_t bAddr = (uint32_t)((wn0 + (lane & 7) + ((lane >> 4) & 1) * 8) * RSB
                                + ((lane >> 3) & 1) * 16);

    for (int t = 0; t < T; t++) {
        asm volatile("cp.async.wait_group 2;" ::: "memory");
        __syncthreads();
        int s = t & (NSTAGE - 1);
        if (t + NSTAGE - 1 < T) load_stage(t + NSTAGE - 1, (t + NSTAGE - 1) & (NSTAGE - 1));

        uint32_t sa = smA + s * STAGE_B + aAddr;
        uint32_t sb2 = smB + s * STAGE_B + bAddr;
        #pragma unroll
        for (int ks = 0; ks < 2; ks++) {
            uint32_t af[4][4], bf[4][2];
            #pragma unroll
            for (int i = 0; i < 4; i++)
                ldmx4(af[i][0], af[i][1], af[i][2], af[i][3],
                      sa + i * 16 * RSB + ks * 32);
            #pragma unroll
            for (int jj = 0; jj < 2; jj++) {
                uint32_t r0, r1, r2, r3;
                ldmx4(r0, r1, r2, r3, sb2 + jj * 16 * RSB + ks * 32);
                bf[jj * 2][0] = r0; bf[jj * 2][1] = r1;
                bf[jj * 2 + 1][0] = r2; bf[jj * 2 + 1][1] = r3;
            }
            #pragma unroll
            for (int i = 0; i < 4; i++)
                #pragma unroll
                for (int j = 0; j < 4; j++)
                    mma_bf16(acc[i][j], af[i], bf[j]);
        }
        __syncthreads();
    }

    // epilogue (stores guarded: r<M, n<N)
    #pragma unroll
    for (int i = 0; i < 4; i++) {
        int r0 = m0 + wm0 + i * 16 + gid;
        int r1 = r0 + 8;
        #pragma unroll
        for (int j = 0; j < 4; j++) {
            int n = n0 + wn0 + j * 8 + tid4 * 2;
            if (n >= N) continue;
            if constexpr (EPI == 0) {
                float* Cz = C + (size_t)z * strC;
                if (r0 < M) {
                    float2 o = make_float2(acc[i][j][0] * scale, acc[i][j][1] * scale);
                    *(float2*)(Cz + (size_t)r0 * N + n) = o;
                }
                if (r1 < M) {
                    float2 o = make_float2(acc[i][j][2] * scale, acc[i][j][3] * scale);
                    *(float2*)(Cz + (size_t)r1 * N + n) = o;
                }
            } else if constexpr (EPI == 1) {
                {
                    int which = r0 >> 8, oc = r0 & 255;
                    float bias = aux[r0];
                    float2 o = make_float2(acc[i][j][0] + bias, acc[i][j][1] + bias);
                    *(float2*)(C + (size_t)which * TOT + (size_t)b * CHW + (size_t)oc * HW + n) = o;
                }
                {
                    int which = r1 >> 8, oc = r1 & 255;
                    float bias = aux[r1];
                    float2 o = make_float2(acc[i][j][2] + bias, acc[i][j][3] + bias);
                    *(float2*)(C + (size_t)which * TOT + (size_t)b * CHW + (size_t)oc * HW + n) = o;
                }
            } else {
                float* Cz = C + (size_t)b * strC;
                const float* Xb = aux + (size_t)b * strAux;
                if (r0 < M) {
                    float2 xv = *(const float2*)(Xb + (size_t)r0 * N + n);
                    float2 o = make_float2(acc[i][j][0] + xv.x, acc[i][j][1] + xv.y);
                    *(float2*)(Cz + (size_t)r0 * N + n) = o;
                }
                if (r1 < M) {
                    float2 xv = *(const float2*)(Xb + (size_t)r1 * N + n);
                    float2 o = make_float2(acc[i][j][2] + xv.x, acc[i][j][3] + xv.y);
                    *(float2*)(Cz + (size_t)r1 * N + n) = o;
                }
            }
        }
    }
}

// ======================= pooled transposed q/k -> bf16 [b][p56][c] =======================
__global__ void __launch_bounds__(256) k_pool_tr() {
    __shared__ float sm[32][33];
    int z = blockIdx.z;
    int b = z >> 1, which = z & 1;
    const float* src = g_qkv + (size_t)which * TOT + (size_t)b * CHW;
    __nv_bfloat16* dst = ((which == 0) ? g_qpT : g_kpT) + (size_t)b * AG * NC;
    int p0 = blockIdx.x * 32, c0 = blockIdx.y * 32;
    int tx = threadIdx.x & 31, ty = threadIdx.x >> 5;
    #pragma unroll
    for (int w = 0; w < 4; w++) {
        int c = c0 + ty + w * 8;
        int p = p0 + tx;
        int y = p / TGD, x56 = p % TGD;
        const float* s = src + (size_t)c * HW + (size_t)(y * 2) * NWW + x56 * 2;
        sm[ty + w * 8][tx] = 0.25f * (s[0] + s[1] + s[NWW] + s[NWW + 1]);
    }
    __syncthreads();
    #pragma unroll
    for (int w = 0; w < 4; w++) {
        int p = p0 + ty + w * 8;
        dst[(size_t)p * NC + c0 + tx] = __float2bfloat16(sm[tx][ty + w * 8]);
    }
}

// pooled v bf16 [b][c][p56]
__global__ void __launch_bounds__(256) k_pool_nat() {
    int i = blockIdx.x * 256 + threadIdx.x;
    if (i >= NB * NC * AG) return;
    int xq = i % TGD;
    int t2 = i / TGD;
    int yq = t2 % TGD;
    int bc = t2 / TGD;
    const float* s = g_qkv + (size_t)2 * TOT + (size_t)bc * HW + (size_t)(yq * 2) * NWW + xq * 2;
    g_vp[i] = __float2bfloat16(0.25f * (s[0] + s[1] + s[NWW] + s[NWW + 1]));
}

// ======================= patch q/k repack bf16: [b][p][c*64+s] =======================
__global__ void __launch_bounds__(256) k_pack() {
    __shared__ float sm[64][33];
    int z = blockIdx.z;
    int b = z >> 1, which = z & 1;
    int c = blockIdx.y;
    int p0 = blockIdx.x * 32;
    const float* src = g_qkv + (size_t)which * TOT + (size_t)b * CHW + (size_t)c * HW;
    __nv_bfloat16* dst = ((which == 0) ? g_qpk : g_kpk) + (size_t)b * PA * DD;
    int tid = threadIdx.x;
    #pragma unroll
    for (int w = 0; w < 8; w++) {
        int ss = (tid >> 5) + w * 8;
        int pp = tid & 31;
        int p = p0 + pp;
        sm[ss][pp] = (p < PA) ? src[ss * PA + p] : 0.f;
    }
    __syncthreads();
    #pragma unroll
    for (int w = 0; w < 8; w++) {
        int pp = (tid >> 6) + w * 4;
        int s2 = tid & 63;
        int p = p0 + pp;
        if (p < PA) dst[(size_t)p * DD + c * 64 + s2] = __float2bfloat16(sm[s2][pp]);
    }
}

// ======================= v bf16 K-padded: [b][d][224] =======================
__global__ void __launch_bounds__(256) k_vconv() {
    size_t i = (size_t)blockIdx.x * 256 + threadIdx.x;
    if (i >= (size_t)NB * DD * PAP) return;
    int p = (int)(i % PAP);
    size_t bd = i / PAP;
    float v = 0.f;
    if (p < PA) v = g_qkv[(size_t)2 * TOT + bd * PA + p];
    g_vpk[i] = __float2bfloat16(v);
}

// ======================= split-K reduce for patch scores =======================
__global__ void __launch_bounds__(256) k_reduce_attp() {
    int i = blockIdx.x * 256 + threadIdx.x;
    if (i >= NB * PA * PA) return;
    int b = i / (PA * PA);
    int off = i - b * (PA * PA);
    float s = 0.f;
    #pragma unroll
    for (int sp = 0; sp < PSPLIT; sp++)
        s += g_attps[((size_t)(b * PSPLIT + sp)) * (PA * PA) + off];
    g_attp[i] = s * 0.0078125f;
}

// ======================= row softmax (fp32 in, bf16 out) =======================
template <int MODE>
__global__ void __launch_bounds__(256) k_softmax() {
    constexpr int N = (MODE == 0) ? PA : AG;
    constexpr int NO = (MODE == 0) ? PAP : AG;
    constexpr int VL = (N + 255) / 256;
    const float* row = ((MODE == 0) ? g_attp : g_attg) + (size_t)blockIdx.x * N;
    __nv_bfloat16* orow = ((MODE == 0) ? g_attp_bf : g_attg_bf) + (size_t)blockIdx.x * NO;
    int t = threadIdx.x;

    float v[VL];
    float mx = -3.4e38f;
    int cnt = 0;
    for (int i = t; i < N; i += 256) { float a = row[i]; v[cnt++] = a; mx = fmaxf(mx, a); }

    __shared__ float sh[256];
    sh[t] = mx; __syncthreads();
    #pragma unroll
    for (int o = 128; o > 0; o >>= 1) { if (t < o) sh[t] = fmaxf(sh[t], sh[t + o]); __syncthreads(); }
    mx = sh[0];
    __syncthreads();

    float s = 0.f; cnt = 0;
    for (int i = t; i < N; i += 256) { float e = __expf(v[cnt] - mx); v[cnt] = e; s += e; cnt++; }
    sh[t] = s; __syncthreads();
    #pragma unroll
    for (int o = 128; o > 0; o >>= 1) { if (t < o) sh[t] += sh[t + o]; __syncthreads(); }
    float inv = 1.f / sh[0];

    cnt = 0;
    for (int i = t; i < NO; i += 256) {
        float o = (i < N) ? v[cnt++] * inv : 0.f;
        orow[i] = __float2bfloat16(o);
    }
}

// ======== combine 0.75*hp + 0.25*bilinear(hg), transpose -> hT bf16 [b][hw][c] ========
__global__ void __launch_bounds__(256) k_combineT() {
    __shared__ float sm[32][33];
    int b = blockIdx.z;
    int hw0 = blockIdx.x * 32, c0 = blockIdx.y * 32;
    int tx = threadIdx.x & 31, ty = threadIdx.x >> 5;
    #pragma unroll
    for (int w = 0; w < 4; w++) {
        int c = c0 + ty + w * 8;
        int hw = hw0 + tx;
        int yh = hw / NWW, xw = hw % NWW;

        int jy = yh >> 1;
        int y0 = (yh & 1) ? jy : jy - 1;
        float wy = (yh & 1) ? 0.25f : 0.75f;
        int y1 = min(y0 + 1, TGD - 1);
        y0 = max(y0, 0);

        int jx = xw >> 1;
        int x0 = (xw & 1) ? jx : jx - 1;
        float wx = (xw & 1) ? 0.25f : 0.75f;
        int x1 = min(x0 + 1, TGD - 1);
        x0 = max(x0, 0);

        const float* g = g_hg + ((size_t)b * NC + c) * AG;
        float v00 = g[y0 * TGD + x0], v01 = g[y0 * TGD + x1];
        float v10 = g[y1 * TGD + x0], v11 = g[y1 * TGD + x1];
        float top = v00 * (1.f - wx) + v01 * wx;
        float bot = v10 * (1.f - wx) + v11 * wx;
        float gv = top * (1.f - wy) + bot * wy;

        sm[ty + w * 8][tx] = 0.75f * g_hp[(size_t)b * CHW + (size_t)c * HW + hw] + 0.25f * gv;
    }
    __syncthreads();
    #pragma unroll
    for (int w = 0; w < 4; w++) {
        int hw = hw0 + ty + w * 8;
        g_hT[(size_t)b * CHW + (size_t)hw * NC + c0 + tx] = __float2bfloat16(sm[tx][ty + w * 8]);
    }
}

// ======================= launch =======================
extern "C" void kernel_launch(void* const* d_in, const int* in_sizes, int n_in,
                              void* d_out, int out_size) {
    const float* x   = (const float*)d_in[0];
    const float* gnw = (const float*)d_in[1];
    const float* gnb = (const float*)d_in[2];
    const float* wq  = (const float*)d_in[3];
    const float* bq  = (const float*)d_in[4];
    const float* wk  = (const float*)d_in[5];
    const float* bk  = (const float*)d_in[6];
    const float* wv  = (const float*)d_in[7];
    const float* bv  = (const float*)d_in[8];
    const float* wp  = (const float*)d_in[9];
    float* out = (float*)d_out;

    void* p;
    cudaGetSymbolAddress(&p, g_xnT);     __nv_bfloat16* xnT    = (__nv_bfloat16*)p;
    cudaGetSymbolAddress(&p, g_wstack);  __nv_bfloat16* wstack = (__nv_bfloat16*)p;
    cudaGetSymbolAddress(&p, g_wp);      __nv_bfloat16* wpb    = (__nv_bfloat16*)p;
    cudaGetSymbolAddress(&p, g_bstack);  float* bstack = (float*)p;
    cudaGetSymbolAddress(&p, g_qkv);     float* qkv    = (float*)p;
    cudaGetSymbolAddress(&p, g_qpT);     __nv_bfloat16* qpT  = (__nv_bfloat16*)p;
    cudaGetSymbolAddress(&p, g_kpT);     __nv_bfloat16* kpT  = (__nv_bfloat16*)p;
    cudaGetSymbolAddress(&p, g_vp);      __nv_bfloat16* vp   = (__nv_bfloat16*)p;
    cudaGetSymbolAddress(&p, g_qpk);     __nv_bfloat16* qpk  = (__nv_bfloat16*)p;
    cudaGetSymbolAddress(&p, g_kpk);     __nv_bfloat16* kpk  = (__nv_bfloat16*)p;
    cudaGetSymbolAddress(&p, g_vpk);     __nv_bfloat16* vpk  = (__nv_bfloat16*)p;
    cudaGetSymbolAddress(&p, g_attps);   float* attps  = (float*)p;
    cudaGetSymbolAddress(&p, g_attg);    float* attg   = (float*)p;
    cudaGetSymbolAddress(&p, g_attp_bf); __nv_bfloat16* attp_bf = (__nv_bfloat16*)p;
    cudaGetSymbolAddress(&p, g_attg_bf); __nv_bfloat16* attg_bf = (__nv_bfloat16*)p;
    cudaGetSymbolAddress(&p, g_hg);      float* hg = (float*)p;
    cudaGetSymbolAddress(&p, g_hp);      float* hp = (float*)p;
    cudaGetSymbolAddress(&p, g_hT);      __nv_bfloat16* hT = (__nv_bfloat16*)p;

    const int SMEM_BYTES = 2 * NSTAGE * STAGE_B;  // 81920
    cudaFuncSetAttribute(gemm_bf<0>, cudaFuncAttributeMaxDynamicSharedMemorySize, SMEM_BYTES);
    cudaFuncSetAttribute(gemm_bf<1>, cudaFuncAttributeMaxDynamicSharedMemorySize, SMEM_BYTES);
    cudaFuncSetAttribute(gemm_bf<2>, cudaFuncAttributeMaxDynamicSharedMemorySize, SMEM_BYTES);

    // GroupNorm + prep
    k_gn_partial<<<dim3(GN_BLKS, NB), 256>>>(x);
    k_gn_final<<<NB, 256>>>(gnw, gnb);
    k_gn_applyT<<<dim3(HW / 32, NC / 32, NB), 256>>>(x);
    k_prep<<<768, 256>>>(wq, wk, wv, bq, bk, bv, wp);

    // QKV: [768, HW] = Wstack[768,256] x xnT[HW,256]^T
    gemm_bf<1><<<dim3(98, 6, NB), 256, SMEM_BYTES>>>(
        wstack, xnT, qkv, 768, HW, 256, 256, 256,
        0, CHW, 0, 1, 1.f, bstack, 0);

    // pooled + repacked operands
    k_pool_tr<<<dim3(AG / 32, NC / 32, NB * 2), 256>>>();
    k_pool_nat<<<(NB * NC * AG + 255) / 256, 256>>>();
    k_pack<<<dim3(7, NC, NB * 2), 256>>>();
    k_vconv<<<(int)(((size_t)NB * DD * PAP + 255) / 256), 256>>>();

    // patch scores (split-K=8) -> reduce -> softmax
    gemm_bf<0><<<dim3(2, 2, NB * PSPLIT), 256, SMEM_BYTES>>>(
        qpk, kpk, attps, PA, PA, PKS, DD, DD,
        (size_t)PA * DD, (size_t)PA * DD, (size_t)PA * PA, PSPLIT, 1.f, nullptr, 0);
    k_reduce_attp<<<(NB * PA * PA + 255) / 256, 256>>>();
    k_softmax<0><<<NB * PA, 256>>>();

    // patch PV: hp[DD, PA] = vpk[DD,224] x attp_bf[PA,224]^T
    gemm_bf<0><<<dim3(2, 128, NB), 256, SMEM_BYTES>>>(
        vpk, attp_bf, hp, DD, PA, PAP, PAP, PAP,
        (size_t)DD * PAP, (size_t)PA * PAP, CHW, 1, 1.f, nullptr, 0);

    // global scores
    gemm_bf<0><<<dim3(25, 25, NB), 256, SMEM_BYTES>>>(
        qpT, kpT, attg, AG, AG, 256, 256, 256,
        (size_t)AG * NC, (size_t)AG * NC, (size_t)AG * AG, 1, 0.0625f, nullptr, 0);
    k_softmax<1><<<NB * AG, 256>>>();

    // global PV: hg[NC, AG] = vp[NC,AG] x attg_bf[AG,AG]^T
    gemm_bf<0><<<dim3(25, 2, NB), 256, SMEM_BYTES>>>(
        vp, attg_bf, hg, NC, AG, AG, AG, AG,
        (size_t)NC * AG, (size_t)AG * AG, (size_t)NC * AG, 1, 1.f, nullptr, 0);

    // combine + transpose
    k_combineT<<<dim3(HW / 32, NC / 32, NB), 256>>>();

    // proj + residual
    gemm_bf<2><<<dim3(98, 2, NB), 256, SMEM_BYTES>>>(
        wpb, hT, out, NC, HW, 256, 256, 256,
        0, CHW, CHW, 1, 1.f, x, CHW);
}